// round 5
// baseline (speedup 1.0000x reference)
#include <cuda_runtime.h>
#include <cstdint>

#define Nn   8192
#define Ee   262144
#define Tt   2048
#define NMAT 151
#define NB1  152
#define NTHR 1024

// ---- scratch (no allocation allowed: device globals) ----
__device__ float g_v[Nn];        // xTB - x
__device__ float g_x1[Nn];       // edge scatter result
__device__ float g_x21[Nn];      // W2@v + b2
__device__ float g_x2[Nn];       // W3@x21 + b3
__device__ float g_x3s;          // LSTM scalar head

// dynamic smem:
//   matvec blocks: float s_v[8192]                      (32 KB)
//   LSTM block   : s_cur[2056] + s_h[16384] + red[33]   (~74 KB)
#define SMEM_BYTES ((2056 + 16384 + 33) * 4)
#define SMEM_MV    (Nn * 4)

__device__ __forceinline__ float tanhap(float x) {
    float y;
    asm("tanh.approx.f32 %0, %1;" : "=f"(y) : "f"(x));
    return y;
}

// ---------------------------------------------------------------------------
// K0: init — zero scatter buffer, compute v = xTB - x
// ---------------------------------------------------------------------------
__global__ void gl_init(const float* __restrict__ x, const float* __restrict__ xTB) {
    int i = blockIdx.x * blockDim.x + threadIdx.x;
    if (i < Nn) {
        g_v[i]  = xTB[i] - x[i];
        g_x1[i] = 0.f;
    }
}

// ---------------------------------------------------------------------------
// warp-per-row matvec, smem input vector, ping-pong double-buffered W loads.
// 64 float4 per lane-row -> 16 chunks of 4.
// ---------------------------------------------------------------------------
__device__ __forceinline__ void matvec_rows_pp(const float* __restrict__ W,
                                               const float4* __restrict__ sv,
                                               const float* __restrict__ b,
                                               float* __restrict__ vout,
                                               int gw, int nw, int lane) {
    for (int row = gw; row < Nn; row += nw) {
        const float4* wr = (const float4*)(W + (size_t)row * Nn) + lane;
        float acc0 = 0.f, acc1 = 0.f;
        float4 a0, a1, a2, a3, b0, b1, b2, b3;

        // prologue: chunk 0 -> a
        a0 = __ldg(wr + 0 * 32); a1 = __ldg(wr + 1 * 32);
        a2 = __ldg(wr + 2 * 32); a3 = __ldg(wr + 3 * 32);

        #pragma unroll 1
        for (int c = 0; c < 7; ++c) {
            int j = c * 8;   // chunk pair base (in float4-index units of 4)
            // load chunk 2c+1 -> b, consume a (chunk 2c)
            b0 = __ldg(wr + (j + 4) * 32); b1 = __ldg(wr + (j + 5) * 32);
            b2 = __ldg(wr + (j + 6) * 32); b3 = __ldg(wr + (j + 7) * 32);
            {
                float4 u;
                u = sv[lane + (j + 0) * 32];
                acc0 = fmaf(a0.x, u.x, acc0); acc1 = fmaf(a0.y, u.y, acc1);
                acc0 = fmaf(a0.z, u.z, acc0); acc1 = fmaf(a0.w, u.w, acc1);
                u = sv[lane + (j + 1) * 32];
                acc0 = fmaf(a1.x, u.x, acc0); acc1 = fmaf(a1.y, u.y, acc1);
                acc0 = fmaf(a1.z, u.z, acc0); acc1 = fmaf(a1.w, u.w, acc1);
                u = sv[lane + (j + 2) * 32];
                acc0 = fmaf(a2.x, u.x, acc0); acc1 = fmaf(a2.y, u.y, acc1);
                acc0 = fmaf(a2.z, u.z, acc0); acc1 = fmaf(a2.w, u.w, acc1);
                u = sv[lane + (j + 3) * 32];
                acc0 = fmaf(a3.x, u.x, acc0); acc1 = fmaf(a3.y, u.y, acc1);
                acc0 = fmaf(a3.z, u.z, acc0); acc1 = fmaf(a3.w, u.w, acc1);
            }
            // load chunk 2c+2 -> a, consume b (chunk 2c+1)
            a0 = __ldg(wr + (j + 8) * 32); a1 = __ldg(wr + (j + 9) * 32);
            a2 = __ldg(wr + (j + 10) * 32); a3 = __ldg(wr + (j + 11) * 32);
            {
                float4 u;
                u = sv[lane + (j + 4) * 32];
                acc0 = fmaf(b0.x, u.x, acc0); acc1 = fmaf(b0.y, u.y, acc1);
                acc0 = fmaf(b0.z, u.z, acc0); acc1 = fmaf(b0.w, u.w, acc1);
                u = sv[lane + (j + 5) * 32];
                acc0 = fmaf(b1.x, u.x, acc0); acc1 = fmaf(b1.y, u.y, acc1);
                acc0 = fmaf(b1.z, u.z, acc0); acc1 = fmaf(b1.w, u.w, acc1);
                u = sv[lane + (j + 6) * 32];
                acc0 = fmaf(b2.x, u.x, acc0); acc1 = fmaf(b2.y, u.y, acc1);
                acc0 = fmaf(b2.z, u.z, acc0); acc1 = fmaf(b2.w, u.w, acc1);
                u = sv[lane + (j + 7) * 32];
                acc0 = fmaf(b3.x, u.x, acc0); acc1 = fmaf(b3.y, u.y, acc1);
                acc0 = fmaf(b3.z, u.z, acc0); acc1 = fmaf(b3.w, u.w, acc1);
            }
        }
        // epilogue: chunks 14 (in a) and 15
        b0 = __ldg(wr + 60 * 32); b1 = __ldg(wr + 61 * 32);
        b2 = __ldg(wr + 62 * 32); b3 = __ldg(wr + 63 * 32);
        {
            float4 u;
            u = sv[lane + 56 * 32];
            acc0 = fmaf(a0.x, u.x, acc0); acc1 = fmaf(a0.y, u.y, acc1);
            acc0 = fmaf(a0.z, u.z, acc0); acc1 = fmaf(a0.w, u.w, acc1);
            u = sv[lane + 57 * 32];
            acc0 = fmaf(a1.x, u.x, acc0); acc1 = fmaf(a1.y, u.y, acc1);
            acc0 = fmaf(a1.z, u.z, acc0); acc1 = fmaf(a1.w, u.w, acc1);
            u = sv[lane + 58 * 32];
            acc0 = fmaf(a2.x, u.x, acc0); acc1 = fmaf(a2.y, u.y, acc1);
            acc0 = fmaf(a2.z, u.z, acc0); acc1 = fmaf(a2.w, u.w, acc1);
            u = sv[lane + 59 * 32];
            acc0 = fmaf(a3.x, u.x, acc0); acc1 = fmaf(a3.y, u.y, acc1);
            acc0 = fmaf(a3.z, u.z, acc0); acc1 = fmaf(a3.w, u.w, acc1);
            u = sv[lane + 60 * 32];
            acc0 = fmaf(b0.x, u.x, acc0); acc1 = fmaf(b0.y, u.y, acc1);
            acc0 = fmaf(b0.z, u.z, acc0); acc1 = fmaf(b0.w, u.w, acc1);
            u = sv[lane + 61 * 32];
            acc0 = fmaf(b1.x, u.x, acc0); acc1 = fmaf(b1.y, u.y, acc1);
            acc0 = fmaf(b1.z, u.z, acc0); acc1 = fmaf(b1.w, u.w, acc1);
            u = sv[lane + 62 * 32];
            acc0 = fmaf(b2.x, u.x, acc0); acc1 = fmaf(b2.y, u.y, acc1);
            acc0 = fmaf(b2.z, u.z, acc0); acc1 = fmaf(b2.w, u.w, acc1);
            u = sv[lane + 63 * 32];
            acc0 = fmaf(b3.x, u.x, acc0); acc1 = fmaf(b3.y, u.y, acc1);
            acc0 = fmaf(b3.z, u.z, acc0); acc1 = fmaf(b3.w, u.w, acc1);
        }

        float acc = acc0 + acc1;
        #pragma unroll
        for (int o = 16; o; o >>= 1) acc += __shfl_down_sync(0xffffffffu, acc, o);
        if (lane == 0) vout[row] = acc + b[row];
    }
}

// ---------------------------------------------------------------------------
// K1: blocks 0..150 scatter + mv1; block 151 LSTM (writes g_x3s)
// ---------------------------------------------------------------------------
__global__ void __launch_bounds__(NTHR, 1)
gl_phase1(const float* __restrict__ x,   const float* __restrict__ cur,
          const int*   __restrict__ ei,  const float* __restrict__ att,
          const float* __restrict__ W2,  const float* __restrict__ b2,
          const float* __restrict__ Wih, const float* __restrict__ Whh,
          const float* __restrict__ bih, const float* __restrict__ bhh,
          const float* __restrict__ W1,  const float* __restrict__ b1) {
    extern __shared__ float smem[];
    const int lane = threadIdx.x & 31;
    const int warp = threadIdx.x >> 5;

    if (blockIdx.x < NMAT) {
        float4* sv = (float4*)smem;
        {   // stage v into smem
            const float4* gv = (const float4*)g_v;
            for (int i = threadIdx.x; i < Nn / 4; i += NTHR) sv[i] = gv[i];
        }
        {   // edge scatter
            int tid  = blockIdx.x * NTHR + threadIdx.x;
            int nthr = NMAT * NTHR;
            for (int e = tid; e < Ee; e += nthr) {
                int s = ei[e];
                int d = ei[Ee + e];
                float m = (__ldg(x + s) - __ldg(x + d)) * __ldg(att + e);
                atomicAdd(&g_x1[d], m);
            }
        }
        __syncthreads();

        int gw = blockIdx.x * (NTHR / 32) + warp;
        int nw = NMAT * (NTHR / 32);
        matvec_rows_pp(W2, sv, b2, g_x21, gw, nw, lane);
    } else {
        // ---------------- LSTM block ----------------
        float* s_cur = smem;                 // [2056]
        float* s_h   = smem + 2056;          // [16384]
        float* s_red = smem + 2056 + 16384;  // [32]

        for (int i = threadIdx.x; i < Tt; i += NTHR) s_cur[i] = cur[i];
        if (threadIdx.x < 8) s_cur[Tt + threadIdx.x] = 0.f;
        __syncthreads();

        if (warp == 0) {
            const int u  = lane & 7;
            const int gt = lane >> 3;
            const bool sig = (gt != 2);
            const float wscale = sig ? 0.5f : 1.0f;
            const float sca = sig ? 0.5f : 1.0f;
            const float scb = sig ? 0.5f : 0.0f;

            float w0 = wscale * Whh[lane * 8 + 0];
            float w1 = wscale * Whh[lane * 8 + 1];
            float w2 = wscale * Whh[lane * 8 + 2];
            float w3 = wscale * Whh[lane * 8 + 3];
            float w4 = wscale * Whh[lane * 8 + 4];
            float w5 = wscale * Whh[lane * 8 + 5];
            float w6 = wscale * Whh[lane * 8 + 6];
            float w7 = wscale * Whh[lane * 8 + 7];
            float a  = wscale * Wih[lane];
            float bb = wscale * (bih[lane] + bhh[lane]);

            float h = 0.f, c = 0.f;
            float xt = s_cur[0];
            float* shp = s_h + u;

            #pragma unroll 2
            for (int t = 0; t < Tt; t++) {
                float pre = fmaf(a, xt, bb);
                float xn  = s_cur[t + 1];

                float h0 = __shfl_sync(0xffffffffu, h, 0);
                float h1 = __shfl_sync(0xffffffffu, h, 1);
                float h2 = __shfl_sync(0xffffffffu, h, 2);
                float h3 = __shfl_sync(0xffffffffu, h, 3);
                float h4 = __shfl_sync(0xffffffffu, h, 4);
                float h5 = __shfl_sync(0xffffffffu, h, 5);
                float h6 = __shfl_sync(0xffffffffu, h, 6);
                float h7 = __shfl_sync(0xffffffffu, h, 7);

                float acc0 = fmaf(w0, h0, pre);
                float acc1 = w1 * h1;
                acc0 = fmaf(w2, h2, acc0);
                acc1 = fmaf(w3, h3, acc1);
                acc0 = fmaf(w4, h4, acc0);
                acc1 = fmaf(w5, h5, acc1);
                acc0 = fmaf(w6, h6, acc0);
                acc1 = fmaf(w7, h7, acc1);
                float z = acc0 + acc1;

                float v = fmaf(tanhap(z), sca, scb);

                float si = __shfl_sync(0xffffffffu, v, u);
                float sf = __shfl_sync(0xffffffffu, v, 8 + u);
                float tg = __shfl_sync(0xffffffffu, v, 16 + u);
                float so = __shfl_sync(0xffffffffu, v, 24 + u);

                c = fmaf(sf, c, si * tg);
                h = so * tanhap(c);

                if (lane < 8) shp[t * 8] = h;   // @P STS (single-instr arm)
                xt = xn;
            }
        }
        __syncthreads();

        float part = 0.f;
        for (int k = threadIdx.x; k < Tt * 8; k += NTHR)
            part = fmaf(__ldg(W1 + k), s_h[k], part);
        #pragma unroll
        for (int o = 16; o; o >>= 1) part += __shfl_down_sync(0xffffffffu, part, o);
        if (lane == 0) s_red[warp] = part;
        __syncthreads();
        if (threadIdx.x == 0) {
            float s = 0.f;
            #pragma unroll
            for (int w = 0; w < NTHR / 32; w++) s += s_red[w];
            g_x3s = s + b1[0];
        }
    }
}

// ---------------------------------------------------------------------------
// K2: mv2 — pure streaming matvec (the bandwidth probe)
// ---------------------------------------------------------------------------
__global__ void __launch_bounds__(NTHR, 1)
gl_phase2(const float* __restrict__ W3, const float* __restrict__ b3) {
    extern __shared__ float smem[];
    float4* sv = (float4*)smem;
    const int lane = threadIdx.x & 31;
    const int warp = threadIdx.x >> 5;

    {
        const float4* gx = (const float4*)g_x21;
        for (int i = threadIdx.x; i < Nn / 4; i += NTHR) sv[i] = gx[i];
    }
    __syncthreads();

    int gw = blockIdx.x * (NTHR / 32) + warp;
    int nw = NB1 * (NTHR / 32);
    matvec_rows_pp(W3, sv, b3, g_x2, gw, nw, lane);
}

// ---------------------------------------------------------------------------
// K3: final combine
// ---------------------------------------------------------------------------
__global__ void gl_combine(const float* __restrict__ x,
                           const float* __restrict__ x30,
                           float* __restrict__ out) {
    int i = blockIdx.x * blockDim.x + threadIdx.x;
    if (i < Nn) out[i] = x[i] + g_x1[i] + g_x2[i] + g_x3s * x30[i];
}

// ---------------------------------------------------------------------------
extern "C" void kernel_launch(void* const* d_in, const int* in_sizes, int n_in,
                              void* d_out, int out_size) {
    const float* x   = (const float*)d_in[0];
    const float* xTB = (const float*)d_in[1];
    const float* cur = (const float*)d_in[2];
    const int*   ei  = (const int*)  d_in[3];
    const float* att = (const float*)d_in[4];
    const float* W2  = (const float*)d_in[5];
    const float* b2  = (const float*)d_in[6];
    const float* W3  = (const float*)d_in[7];
    const float* b3  = (const float*)d_in[8];
    const float* Wih = (const float*)d_in[9];
    const float* Whh = (const float*)d_in[10];
    const float* bih = (const float*)d_in[11];
    const float* bhh = (const float*)d_in[12];
    const float* W1  = (const float*)d_in[13];
    const float* b1  = (const float*)d_in[14];
    const float* x30 = (const float*)d_in[15];
    float* out = (float*)d_out;

    cudaFuncSetAttribute(gl_phase1, cudaFuncAttributeMaxDynamicSharedMemorySize, SMEM_BYTES);
    cudaFuncSetAttribute(gl_phase2, cudaFuncAttributeMaxDynamicSharedMemorySize, SMEM_MV);

    gl_init<<<(Nn + 255) / 256, 256>>>(x, xTB);
    gl_phase1<<<NB1, NTHR, SMEM_BYTES>>>(x, cur, ei, att, W2, b2,
                                         Wih, Whh, bih, bhh, W1, b1);
    gl_phase2<<<NB1, NTHR, SMEM_MV>>>(W3, b3);
    gl_combine<<<(Nn + 255) / 256, 256>>>(x, x30, out);
}

// round 6
// speedup vs baseline: 2.0143x; 2.0143x over previous
#include <cuda_runtime.h>
#include <cstdint>

#define Nn   8192
#define Ee   262144
#define Tt   2048
#define NBLK 152
#define NMAT 151
#define NTHR 512

// ---- scratch (device globals; no allocation allowed) ----
__device__ float g_v[Nn];        // xTB - x
__device__ float g_x1[Nn];       // edge scatter result
__device__ float g_x21[Nn];      // W2@v + b2
__device__ float g_x2[Nn];       // W3@x21 + b3
__device__ int   g_bar1;         // barrier between matvec1 and matvec2
__device__ int   g_done;         // matvec blocks finished

// dynamic smem:
//   matvec blocks: float s_v[8192]                          (32 KB)
//   LSTM block   : s_cur[2048] + s_h[8+16384] + red[17]     (~74 KB)
#define SMEM_BYTES ((2048 + 8 + 16384 + 17) * 4)
#define SMEM_MV    (Nn * 4)

__device__ __forceinline__ float tanhap(float x) {
    float y;
    asm("tanh.approx.f32 %0, %1;" : "=f"(y) : "f"(x));
    return y;
}

// ---------------------------------------------------------------------------
// K0: init — zero scatter buffer + flags, compute v = xTB - x
// ---------------------------------------------------------------------------
__global__ void gl_init(const float* __restrict__ x, const float* __restrict__ xTB) {
    int i = blockIdx.x * blockDim.x + threadIdx.x;
    if (i < Nn) {
        g_v[i]  = xTB[i] - x[i];
        g_x1[i] = 0.f;
    }
    if (i == 0) { g_bar1 = 0; g_done = 0; }
}

// ---------------------------------------------------------------------------
// warp-per-row matvec, smem input vector, 16-deep front-batched W loads
// (needs ~90 regs -> 512 thr/block, 1 block/SM)
// ---------------------------------------------------------------------------
__device__ __forceinline__ void matvec_rows16(const float* __restrict__ W,
                                              const float4* __restrict__ sv,
                                              const float* __restrict__ b,
                                              float* __restrict__ vout,
                                              int gw, int nw, int lane) {
    for (int row = gw; row < Nn; row += nw) {
        const float4* wr = (const float4*)(W + (size_t)row * Nn) + lane;
        float acc0 = 0.f, acc1 = 0.f;
        #pragma unroll 1
        for (int c = 0; c < 4; ++c) {
            float4 w[16];
            #pragma unroll
            for (int k = 0; k < 16; ++k)
                w[k] = __ldg(wr + (c * 16 + k) * 32);   // 16 LDG.128 in flight
            #pragma unroll
            for (int k = 0; k < 16; ++k) {
                float4 u = sv[lane + (c * 16 + k) * 32];
                acc0 = fmaf(w[k].x, u.x, acc0);
                acc1 = fmaf(w[k].y, u.y, acc1);
                acc0 = fmaf(w[k].z, u.z, acc0);
                acc1 = fmaf(w[k].w, u.w, acc1);
            }
        }
        float acc = acc0 + acc1;
        #pragma unroll
        for (int o = 16; o; o >>= 1) acc += __shfl_down_sync(0xffffffffu, acc, o);
        if (lane == 0) vout[row] = acc + b[row];
    }
}

// ---------------------------------------------------------------------------
// K1: mega kernel.
//   blocks 0..150 : edge scatter, matvec1, spin barrier, matvec2, done flag
//   block  151    : LSTM (warp 0, gate-per-lane, smem h-history broadcast),
//                   W1 dot, wait, final combine
// ---------------------------------------------------------------------------
__global__ void __launch_bounds__(NTHR, 1)
gl_main(const float* __restrict__ x,   const float* __restrict__ cur,
        const int*   __restrict__ ei,  const float* __restrict__ att,
        const float* __restrict__ W2,  const float* __restrict__ b2,
        const float* __restrict__ W3,  const float* __restrict__ b3,
        const float* __restrict__ Wih, const float* __restrict__ Whh,
        const float* __restrict__ bih, const float* __restrict__ bhh,
        const float* __restrict__ W1,  const float* __restrict__ b1,
        const float* __restrict__ x30, float* __restrict__ out) {
    extern __shared__ float smem[];
    const int lane = threadIdx.x & 31;
    const int warp = threadIdx.x >> 5;

    if (blockIdx.x < NMAT) {
        // ---------------- matvec / scatter blocks ----------------
        float4* sv = (float4*)smem;
        {   // stage v into smem
            const float4* gv = (const float4*)g_v;
            for (int i = threadIdx.x; i < Nn / 4; i += NTHR) sv[i] = gv[i];
        }
        {   // edge scatter
            int tid  = blockIdx.x * NTHR + threadIdx.x;
            int nthr = NMAT * NTHR;
            for (int e = tid; e < Ee; e += nthr) {
                int s = ei[e];
                int d = ei[Ee + e];
                float m = (__ldg(x + s) - __ldg(x + d)) * __ldg(att + e);
                atomicAdd(&g_x1[d], m);
            }
        }
        __syncthreads();

        int gw = blockIdx.x * (NTHR / 32) + warp;
        int nw = NMAT * (NTHR / 32);
        matvec_rows16(W2, sv, b2, g_x21, gw, nw, lane);

        __syncthreads();
        if (threadIdx.x == 0) {
            __threadfence();
            atomicAdd(&g_bar1, 1);
            while (atomicAdd(&g_bar1, 0) < NMAT) {}
            __threadfence();
        }
        __syncthreads();

        {   // stage x21 into smem
            const float4* gx = (const float4*)g_x21;
            for (int i = threadIdx.x; i < Nn / 4; i += NTHR) sv[i] = gx[i];
        }
        __syncthreads();

        matvec_rows16(W3, sv, b3, g_x2, gw, nw, lane);

        __syncthreads();
        if (threadIdx.x == 0) {
            __threadfence();
            atomicAdd(&g_done, 1);
        }
    } else {
        // ---------------- LSTM block ----------------
        float* s_cur = smem;                        // [2048]
        float* s_h   = smem + 2048;                 // [8 + 16384]: slot t holds h(t-1)
        float* s_red = smem + 2048 + 8 + 16384;     // [16]
        float* s_x3  = s_red + 16;

        for (int i = threadIdx.x; i < Tt; i += NTHR) s_cur[i] = cur[i];
        if (threadIdx.x < 8) s_h[threadIdx.x] = 0.f;   // h(-1) = 0
        __syncthreads();

        if (warp == 0) {
            // gate-per-lane: lane = gt*8 + u
            // sigmoid gates (gt 0,1,3) via 0.5*tanh(z/2)+0.5; gate 2 tanh
            const int u  = lane & 7;
            const int gt = lane >> 3;
            const bool sig = (gt != 2);
            const float wscale = sig ? 0.5f : 1.0f;
            const float sca = sig ? 0.5f : 1.0f;
            const float scb = sig ? 0.5f : 0.0f;

            float w0 = wscale * Whh[lane * 8 + 0];
            float w1 = wscale * Whh[lane * 8 + 1];
            float w2 = wscale * Whh[lane * 8 + 2];
            float w3 = wscale * Whh[lane * 8 + 3];
            float w4 = wscale * Whh[lane * 8 + 4];
            float w5 = wscale * Whh[lane * 8 + 5];
            float w6 = wscale * Whh[lane * 8 + 6];
            float w7 = wscale * Whh[lane * 8 + 7];
            float a  = wscale * Wih[lane];
            float bb = wscale * (bih[lane] + bhh[lane]);

            float c = 0.f;
            // shared-memory addresses (32-bit smem space)
            uint32_t hrd = (uint32_t)__cvta_generic_to_shared(s_h);          // read h(t-1) at +t*32B
            uint32_t hwr = (uint32_t)__cvta_generic_to_shared(s_h + 8 + u);  // write h(t) at +t*32B

            #pragma unroll 4
            for (int t = 0; t < Tt; t++) {
                float xt = s_cur[t];
                // h(t-1) broadcast via smem history (written last iteration)
                float4 hlo, hhi;
                asm volatile("ld.shared.v4.f32 {%0,%1,%2,%3}, [%4];"
                             : "=f"(hlo.x), "=f"(hlo.y), "=f"(hlo.z), "=f"(hlo.w)
                             : "r"(hrd + t * 32));
                asm volatile("ld.shared.v4.f32 {%0,%1,%2,%3}, [%4];"
                             : "=f"(hhi.x), "=f"(hhi.y), "=f"(hhi.z), "=f"(hhi.w)
                             : "r"(hrd + t * 32 + 16));

                float pre  = fmaf(a, xt, bb);
                float acc0 = fmaf(w0, hlo.x, pre);
                float acc1 = w1 * hlo.y;
                acc0 = fmaf(w2, hlo.z, acc0);
                acc1 = fmaf(w3, hlo.w, acc1);
                acc0 = fmaf(w4, hhi.x, acc0);
                acc1 = fmaf(w5, hhi.y, acc1);
                acc0 = fmaf(w6, hhi.z, acc0);
                acc1 = fmaf(w7, hhi.w, acc1);
                float z = acc0 + acc1;

                float v = fmaf(tanhap(z), sca, scb);

                float si = __shfl_sync(0xffffffffu, v, u);
                float sf = __shfl_sync(0xffffffffu, v, 8 + u);
                float tg = __shfl_sync(0xffffffffu, v, 16 + u);
                float so = __shfl_sync(0xffffffffu, v, 24 + u);

                c = fmaf(sf, c, si * tg);
                float h = so * tanhap(c);

                // lanes 0..7 publish h(t) (predicated single STS, no branch)
                asm volatile("{ .reg .pred p; setp.lt.s32 p, %0, 8;"
                             "  @p st.shared.f32 [%1], %2; }"
                             :: "r"(lane), "r"(hwr + t * 32), "f"(h));
            }
        }
        __syncthreads();   // s_h visible block-wide

        // x3 scalar = W1 · hs_flat + b1   (history lives at s_h+8)
        const float* hist = s_h + 8;
        float part = 0.f;
        for (int k = threadIdx.x; k < Tt * 8; k += NTHR)
            part = fmaf(__ldg(W1 + k), hist[k], part);
        #pragma unroll
        for (int o = 16; o; o >>= 1) part += __shfl_down_sync(0xffffffffu, part, o);
        if (lane == 0) s_red[warp] = part;
        __syncthreads();
        if (threadIdx.x == 0) {
            float s = 0.f;
            #pragma unroll
            for (int w = 0; w < NTHR / 32; w++) s += s_red[w];
            *s_x3 = s + b1[0];
            while (atomicAdd(&g_done, 0) < NMAT) {}  // wait for matvec blocks
            __threadfence();
        }
        __syncthreads();

        float x3 = *s_x3;
        for (int i = threadIdx.x; i < Nn; i += NTHR)
            out[i] = x[i] + g_x1[i] + g_x2[i] + x3 * x30[i];
    }
}

// ---------------------------------------------------------------------------
extern "C" void kernel_launch(void* const* d_in, const int* in_sizes, int n_in,
                              void* d_out, int out_size) {
    const float* x   = (const float*)d_in[0];
    const float* xTB = (const float*)d_in[1];
    const float* cur = (const float*)d_in[2];
    const int*   ei  = (const int*)  d_in[3];
    const float* att = (const float*)d_in[4];
    const float* W2  = (const float*)d_in[5];
    const float* b2  = (const float*)d_in[6];
    const float* W3  = (const float*)d_in[7];
    const float* b3  = (const float*)d_in[8];
    const float* Wih = (const float*)d_in[9];
    const float* Whh = (const float*)d_in[10];
    const float* bih = (const float*)d_in[11];
    const float* bhh = (const float*)d_in[12];
    const float* W1  = (const float*)d_in[13];
    const float* b1  = (const float*)d_in[14];
    const float* x30 = (const float*)d_in[15];
    float* out = (float*)d_out;

    cudaFuncSetAttribute(gl_main, cudaFuncAttributeMaxDynamicSharedMemorySize,
                         SMEM_BYTES);

    gl_init<<<(Nn + 255) / 256, 256>>>(x, xTB);
    gl_main<<<NBLK, NTHR, SMEM_BYTES>>>(x, cur, ei, att, W2, b2, W3, b3,
                                        Wih, Whh, bih, bhh, W1, b1, x30, out);
}